// round 1
// baseline (speedup 1.0000x reference)
#include <cuda_runtime.h>
#include <cuda_bf16.h>
#include <math.h>

#define N_EXPERTS 8
#define TOPK      2
#define IN_DIM    512
#define HID_DIM   1024
#define OUT_DIM   512
#define NTOK      16384

#define TILE_M 128
#define MAX_TILES ((NTOK * TOPK) / TILE_M + N_EXPERTS)   // 264
#define PADDED    (MAX_TILES * TILE_M)                    // 33792

// ---------------- device scratch (no allocations allowed) ----------------
__device__ int   g_topk_idx[NTOK * TOPK];
__device__ float g_topk_w[NTOK * TOPK];
__device__ int   g_counts[N_EXPERTS];
__device__ int   g_cursor[N_EXPERTS];
__device__ int   g_tile_expert[MAX_TILES];
__device__ int   g_tile_base[MAX_TILES];
__device__ int   g_num_tiles;
__device__ int   g_assign_token[PADDED];
__device__ float g_assign_w[PADDED];
__device__ float g_hidden[(size_t)PADDED * HID_DIM];      // ~138 MB scratch

// ---------------- K0: zero output, counts, assignment padding ------------
__global__ void zero_kernel(float* __restrict__ out) {
    size_t idx = (size_t)blockIdx.x * blockDim.x + threadIdx.x;
    size_t total = (size_t)NTOK * OUT_DIM;
    if (idx < total) out[idx] = 0.0f;
    if (idx < PADDED) g_assign_token[idx] = -1;
    if (idx < N_EXPERTS) g_counts[idx] = 0;
}

// ---------------- K1: gating — one warp per token -------------------------
__global__ void gating_kernel(const float* __restrict__ x,
                              const float* __restrict__ gw,
                              const float* __restrict__ gb) {
    int token = blockIdx.x * (blockDim.x >> 5) + (threadIdx.x >> 5);
    if (token >= NTOK) return;
    int lane = threadIdx.x & 31;

    float s[N_EXPERTS];
#pragma unroll
    for (int e = 0; e < N_EXPERTS; e++) s[e] = 0.0f;

    const float* xr = x + (size_t)token * IN_DIM;
    for (int i = lane; i < IN_DIM; i += 32) {
        float xv = xr[i];
        const float* g = gw + (size_t)i * N_EXPERTS;
#pragma unroll
        for (int e = 0; e < N_EXPERTS; e++) s[e] += xv * g[e];
    }
#pragma unroll
    for (int off = 16; off > 0; off >>= 1) {
#pragma unroll
        for (int e = 0; e < N_EXPERTS; e++)
            s[e] += __shfl_xor_sync(0xFFFFFFFFu, s[e], off);
    }
    if (lane == 0) {
#pragma unroll
        for (int e = 0; e < N_EXPERTS; e++) s[e] += gb[e];
        // stable top-2 (first occurrence wins ties, matching jax top_k)
        float v0 = -INFINITY; int i0 = -1;
#pragma unroll
        for (int e = 0; e < N_EXPERTS; e++)
            if (s[e] > v0) { v0 = s[e]; i0 = e; }
        float v1 = -INFINITY; int i1 = -1;
#pragma unroll
        for (int e = 0; e < N_EXPERTS; e++)
            if (e != i0 && s[e] > v1) { v1 = s[e]; i1 = e; }

        float e1 = expf(v1 - v0);        // v0 >= v1
        float inv = 1.0f / (1.0f + e1);
        float w0 = inv;
        float w1 = e1 * inv;

        g_topk_idx[token * 2 + 0] = i0;
        g_topk_idx[token * 2 + 1] = i1;
        g_topk_w[token * 2 + 0] = w0;
        g_topk_w[token * 2 + 1] = w1;
        atomicAdd(&g_counts[i0], 1);
        atomicAdd(&g_counts[i1], 1);
    }
}

// ---------------- K2: setup — tile table, cursors, aux loss ---------------
__global__ void setup_kernel(float* __restrict__ out, int out_size) {
    if (threadIdx.x != 0 || blockIdx.x != 0) return;
    int nt = 0, off = 0;
    for (int e = 0; e < N_EXPERTS; e++) {
        int c = g_counts[e];
        int tiles = (c + TILE_M - 1) / TILE_M;
        g_cursor[e] = off;
        for (int i = 0; i < tiles; i++) {
            g_tile_expert[nt] = e;
            g_tile_base[nt] = off + i * TILE_M;
            nt++;
        }
        off += tiles * TILE_M;
    }
    g_num_tiles = nt;

    float aux = 0.0f;
    for (int e = 0; e < N_EXPERTS; e++) {
        float f = (float)g_counts[e] / (float)(NTOK * TOPK) - 1.0f / N_EXPERTS;
        aux += f * f;
    }
    aux *= (1.0f / N_EXPERTS);
    if (out_size > NTOK * OUT_DIM) out[(size_t)NTOK * OUT_DIM] = aux;
}

// ---------------- K3: scatter tokens to expert segments -------------------
__global__ void scatter_kernel() {
    int t = blockIdx.x * blockDim.x + threadIdx.x;
    if (t >= NTOK) return;
#pragma unroll
    for (int k = 0; k < TOPK; k++) {
        int e = g_topk_idx[t * 2 + k];
        int pos = atomicAdd(&g_cursor[e], 1);
        g_assign_token[pos] = t;
        g_assign_w[pos] = g_topk_w[t * 2 + k];
    }
}

__device__ __forceinline__ float gelu_exact(float v) {
    return 0.5f * v * (1.0f + erff(v * 0.70710678118654752440f));
}

// ---------------- K4: GEMM1  h = gelu(x_sel @ w1[e] + b1[e]) --------------
// grid (MAX_TILES, HID_DIM/128), block 256, 128x128x8 fp32 tiles.
__global__ __launch_bounds__(256) void gemm1_kernel(
    const float* __restrict__ x,
    const float* __restrict__ w1,
    const float* __restrict__ b1) {
    __shared__ float As[8][TILE_M];
    __shared__ float Bs[8][128];
    __shared__ int toks[TILE_M];

    int tile = blockIdx.x;
    if (tile >= g_num_tiles) return;
    int e = g_tile_expert[tile];
    int base = g_tile_base[tile];
    int n0 = blockIdx.y * 128;
    int tid = threadIdx.x;

    if (tid < TILE_M) toks[tid] = g_assign_token[base + tid];
    __syncthreads();

    float acc[8][8];
#pragma unroll
    for (int i = 0; i < 8; i++)
#pragma unroll
        for (int j = 0; j < 8; j++) acc[i][j] = 0.0f;

    int ty = tid >> 4, tx = tid & 15;
    int arow = tid >> 1, aseg = (tid & 1) * 4;
    int brow = tid >> 5, bcol = (tid & 31) * 4;
    int atok = toks[arow];
    const float* wbase = w1 + (size_t)e * IN_DIM * HID_DIM + n0;
    const float* abase = (atok >= 0) ? (x + (size_t)atok * IN_DIM + aseg) : nullptr;

    for (int k = 0; k < IN_DIM; k += 8) {
        float4 av = make_float4(0.f, 0.f, 0.f, 0.f);
        if (abase) av = *(const float4*)(abase + k);
        As[aseg + 0][arow] = av.x;
        As[aseg + 1][arow] = av.y;
        As[aseg + 2][arow] = av.z;
        As[aseg + 3][arow] = av.w;
        float4 bv = *(const float4*)(wbase + (size_t)(k + brow) * HID_DIM + bcol);
        *(float4*)&Bs[brow][bcol] = bv;
        __syncthreads();
#pragma unroll
        for (int kk = 0; kk < 8; kk++) {
            float a[8], b[8];
#pragma unroll
            for (int i = 0; i < 8; i++) a[i] = As[kk][ty * 8 + i];
#pragma unroll
            for (int j = 0; j < 8; j++) b[j] = Bs[kk][tx * 8 + j];
#pragma unroll
            for (int i = 0; i < 8; i++)
#pragma unroll
                for (int j = 0; j < 8; j++) acc[i][j] += a[i] * b[j];
        }
        __syncthreads();
    }

#pragma unroll
    for (int i = 0; i < 8; i++) {
        int row = ty * 8 + i;
        float* hrow = &g_hidden[(size_t)(base + row) * HID_DIM + n0];
#pragma unroll
        for (int j = 0; j < 8; j++) {
            int col = tx * 8 + j;
            float v = acc[i][j] + b1[(size_t)e * HID_DIM + n0 + col];
            hrow[col] = gelu_exact(v);
        }
    }
}

// ---------------- K5: GEMM2  out += w * (h @ w2[e] + b2[e]) ---------------
// grid (MAX_TILES, OUT_DIM/128), block 256.
__global__ __launch_bounds__(256) void gemm2_kernel(
    const float* __restrict__ w2,
    const float* __restrict__ b2,
    float* __restrict__ out) {
    __shared__ float As[8][TILE_M];
    __shared__ float Bs[8][128];
    __shared__ int toks[TILE_M];
    __shared__ float wts[TILE_M];

    int tile = blockIdx.x;
    if (tile >= g_num_tiles) return;
    int e = g_tile_expert[tile];
    int base = g_tile_base[tile];
    int n0 = blockIdx.y * 128;
    int tid = threadIdx.x;

    if (tid < TILE_M) {
        toks[tid] = g_assign_token[base + tid];
        wts[tid] = g_assign_w[base + tid];
    }
    __syncthreads();

    float acc[8][8];
#pragma unroll
    for (int i = 0; i < 8; i++)
#pragma unroll
        for (int j = 0; j < 8; j++) acc[i][j] = 0.0f;

    int ty = tid >> 4, tx = tid & 15;
    int arow = tid >> 1, aseg = (tid & 1) * 4;
    int brow = tid >> 5, bcol = (tid & 31) * 4;
    const float* abase = &g_hidden[(size_t)(base + arow) * HID_DIM + aseg];
    const float* wbase = w2 + (size_t)e * HID_DIM * OUT_DIM + n0;

    for (int k = 0; k < HID_DIM; k += 8) {
        float4 av = *(const float4*)(abase + k);
        As[aseg + 0][arow] = av.x;
        As[aseg + 1][arow] = av.y;
        As[aseg + 2][arow] = av.z;
        As[aseg + 3][arow] = av.w;
        float4 bv = *(const float4*)(wbase + (size_t)(k + brow) * OUT_DIM + bcol);
        *(float4*)&Bs[brow][bcol] = bv;
        __syncthreads();
#pragma unroll
        for (int kk = 0; kk < 8; kk++) {
            float a[8], b[8];
#pragma unroll
            for (int i = 0; i < 8; i++) a[i] = As[kk][ty * 8 + i];
#pragma unroll
            for (int j = 0; j < 8; j++) b[j] = Bs[kk][tx * 8 + j];
#pragma unroll
            for (int i = 0; i < 8; i++)
#pragma unroll
                for (int j = 0; j < 8; j++) acc[i][j] += a[i] * b[j];
        }
        __syncthreads();
    }

#pragma unroll
    for (int i = 0; i < 8; i++) {
        int row = ty * 8 + i;
        int t = toks[row];
        if (t < 0) continue;
        float wr = wts[row];
        float* orow = out + (size_t)t * OUT_DIM + n0;
#pragma unroll
        for (int j = 0; j < 8; j++) {
            int col = tx * 8 + j;
            float v = (acc[i][j] + b2[(size_t)e * OUT_DIM + n0 + col]) * wr;
            atomicAdd(&orow[col], v);
        }
    }
}

// ---------------- launch ---------------------------------------------------
extern "C" void kernel_launch(void* const* d_in, const int* in_sizes, int n_in,
                              void* d_out, int out_size) {
    const float* x      = (const float*)d_in[0];
    const float* gate_w = (const float*)d_in[1];
    const float* gate_b = (const float*)d_in[2];
    const float* w1     = (const float*)d_in[3];
    const float* b1     = (const float*)d_in[4];
    const float* w2     = (const float*)d_in[5];
    const float* b2     = (const float*)d_in[6];
    float* out = (float*)d_out;

    // K0: zero out + reset per-launch device state (graph-replay safe)
    {
        size_t total = (size_t)NTOK * OUT_DIM;
        int blocks = (int)((total + 255) / 256);
        zero_kernel<<<blocks, 256>>>(out);
    }
    // K1: gating — 8 warps per block
    gating_kernel<<<NTOK / 8, 256>>>(x, gate_w, gate_b);
    // K2: setup tile table + aux loss
    setup_kernel<<<1, 32>>>(out, out_size);
    // K3: scatter assignments
    scatter_kernel<<<NTOK / 256, 256>>>();
    // K4: GEMM1
    {
        dim3 grid(MAX_TILES, HID_DIM / 128);
        gemm1_kernel<<<grid, 256>>>(x, w1, b1);
    }
    // K5: GEMM2
    {
        dim3 grid(MAX_TILES, OUT_DIM / 128);
        gemm2_kernel<<<grid, 256>>>(w2, b2, out);
    }
}

// round 5
// speedup vs baseline: 1.0842x; 1.0842x over previous
#include <cuda_runtime.h>
#include <cuda_bf16.h>
#include <mma.h>
#include <math.h>
#include <stdint.h>

using namespace nvcuda;

#define N_EXPERTS 8
#define TOPK      2
#define IN_DIM    512
#define HID_DIM   1024
#define OUT_DIM   512
#define NTOK      16384

#define TILE_M 128
#define TILE_N 128
#define MAX_TILES ((NTOK * TOPK) / TILE_M + N_EXPERTS)   // 264
#define PADDED    (MAX_TILES * TILE_M)                    // 33792

#define KCH 32                    // K elements per staged chunk
#define A_LD 40                   // padded lds for A tiles (bf16)
#define B_LD 136                  // padded lds for B tiles (bf16)

// ---------------- device scratch ----------------
__device__ int   g_topk_idx[NTOK * TOPK];
__device__ float g_topk_w[NTOK * TOPK];
__device__ int   g_counts[N_EXPERTS];
__device__ int   g_cursor[N_EXPERTS];
__device__ int   g_tile_expert[MAX_TILES];
__device__ int   g_tile_base[MAX_TILES];
__device__ int   g_num_tiles;
__device__ int   g_assign_token[PADDED];
__device__ float g_assign_w[PADDED];
__device__ float g_hidden[(size_t)PADDED * HID_DIM];

__device__ __forceinline__ float gelu_exact(float v) {
    return 0.5f * v * (1.0f + erff(v * 0.70710678118654752440f));
}
__device__ __forceinline__ void split_bf16(float v, __nv_bfloat16& h, __nv_bfloat16& l) {
    h = __float2bfloat16(v);
    l = __float2bfloat16(v - __bfloat162float(h));
}

// ---------------- K0: zero output, counts, assignment padding ------------
__global__ void zero_kernel(float* __restrict__ out) {
    size_t idx = (size_t)blockIdx.x * blockDim.x + threadIdx.x;
    size_t total = (size_t)NTOK * OUT_DIM;
    if (idx < total) out[idx] = 0.0f;
    if (idx < PADDED) g_assign_token[idx] = -1;
    if (idx < N_EXPERTS) g_counts[idx] = 0;
}

// ---------------- K1: gating — one warp per token -------------------------
__global__ void gating_kernel(const float* __restrict__ x,
                              const float* __restrict__ gw,
                              const float* __restrict__ gb) {
    int token = blockIdx.x * (blockDim.x >> 5) + (threadIdx.x >> 5);
    if (token >= NTOK) return;
    int lane = threadIdx.x & 31;
    float s[N_EXPERTS];
#pragma unroll
    for (int e = 0; e < N_EXPERTS; e++) s[e] = 0.0f;
    const float* xr = x + (size_t)token * IN_DIM;
    for (int i = lane; i < IN_DIM; i += 32) {
        float xv = xr[i];
        const float* g = gw + (size_t)i * N_EXPERTS;
#pragma unroll
        for (int e = 0; e < N_EXPERTS; e++) s[e] += xv * g[e];
    }
#pragma unroll
    for (int off = 16; off > 0; off >>= 1)
#pragma unroll
        for (int e = 0; e < N_EXPERTS; e++)
            s[e] += __shfl_xor_sync(0xFFFFFFFFu, s[e], off);
    if (lane == 0) {
#pragma unroll
        for (int e = 0; e < N_EXPERTS; e++) s[e] += gb[e];
        float v0 = -INFINITY; int i0 = -1;
#pragma unroll
        for (int e = 0; e < N_EXPERTS; e++)
            if (s[e] > v0) { v0 = s[e]; i0 = e; }
        float v1 = -INFINITY; int i1 = -1;
#pragma unroll
        for (int e = 0; e < N_EXPERTS; e++)
            if (e != i0 && s[e] > v1) { v1 = s[e]; i1 = e; }
        float e1 = expf(v1 - v0);
        float inv = 1.0f / (1.0f + e1);
        g_topk_idx[token * 2 + 0] = i0;
        g_topk_idx[token * 2 + 1] = i1;
        g_topk_w[token * 2 + 0] = inv;
        g_topk_w[token * 2 + 1] = e1 * inv;
        atomicAdd(&g_counts[i0], 1);
        atomicAdd(&g_counts[i1], 1);
    }
}

// ---------------- K2: setup — tile table, cursors, aux loss ---------------
__global__ void setup_kernel(float* __restrict__ out, int out_size) {
    if (threadIdx.x != 0 || blockIdx.x != 0) return;
    int nt = 0, off = 0;
    for (int e = 0; e < N_EXPERTS; e++) {
        int c = g_counts[e];
        int tiles = (c + TILE_M - 1) / TILE_M;
        g_cursor[e] = off;
        for (int i = 0; i < tiles; i++) {
            g_tile_expert[nt] = e;
            g_tile_base[nt] = off + i * TILE_M;
            nt++;
        }
        off += tiles * TILE_M;
    }
    g_num_tiles = nt;
    float aux = 0.0f;
    for (int e = 0; e < N_EXPERTS; e++) {
        float f = (float)g_counts[e] / (float)(NTOK * TOPK) - 1.0f / N_EXPERTS;
        aux += f * f;
    }
    aux *= (1.0f / N_EXPERTS);
    if (out_size > NTOK * OUT_DIM) out[(size_t)NTOK * OUT_DIM] = aux;
}

// ---------------- K3: scatter tokens to expert segments -------------------
__global__ void scatter_kernel() {
    int t = blockIdx.x * blockDim.x + threadIdx.x;
    if (t >= NTOK) return;
#pragma unroll
    for (int k = 0; k < TOPK; k++) {
        int e = g_topk_idx[t * 2 + k];
        int pos = atomicAdd(&g_cursor[e], 1);
        g_assign_token[pos] = t;
        g_assign_w[pos] = g_topk_w[t * 2 + k];
    }
}

// ---------------- K4: GEMM1  h = gelu(x_sel @ w1[e] + b1[e]) --------------
// grid (MAX_TILES, HID_DIM/128), block 256 (8 warps: wm=wid&3, wn=wid>>2)
__global__ __launch_bounds__(256) void gemm1_kernel(
    const float* __restrict__ x,
    const float* __restrict__ w1,
    const float* __restrict__ b1) {
    __shared__ __nv_bfloat16 Ah[TILE_M][A_LD];
    __shared__ __nv_bfloat16 Al[TILE_M][A_LD];
    __shared__ __nv_bfloat16 Bh[KCH][B_LD];
    __shared__ __nv_bfloat16 Bl[KCH][B_LD];
    __shared__ float cpatch[8][16 * 16];
    __shared__ int toks[TILE_M];

    int tile = blockIdx.x;
    if (tile >= g_num_tiles) return;
    int e = g_tile_expert[tile];
    int base = g_tile_base[tile];
    int n0 = blockIdx.y * TILE_N;
    int tid = threadIdx.x;
    int lane = tid & 31, wid = tid >> 5;
    int wm = wid & 3, wn = wid >> 2;

    if (tid < TILE_M) toks[tid] = g_assign_token[base + tid];
    __syncthreads();

    wmma::fragment<wmma::accumulator, 16, 16, 16, float> acc[2][4];
#pragma unroll
    for (int i = 0; i < 2; i++)
#pragma unroll
        for (int j = 0; j < 4; j++) wmma::fill_fragment(acc[i][j], 0.0f);

    int arow = tid >> 1, acseg = (tid & 1) * 16;   // A: 128 rows x 32 cols
    int brow = tid >> 3, bcseg = (tid & 7) * 16;   // B: 32 rows x 128 cols
    int atok = toks[arow];
    const float* arp = (atok >= 0) ? (x + (size_t)atok * IN_DIM + acseg) : nullptr;
    const float* wbase = w1 + (size_t)e * IN_DIM * HID_DIM + n0 + bcseg;

    for (int k0 = 0; k0 < IN_DIM; k0 += KCH) {
        // stage A (fp32 -> bf16 hi/lo)
#pragma unroll
        for (int c4 = 0; c4 < 16; c4 += 4) {
            float4 v = arp ? *(const float4*)(arp + k0 + c4)
                           : make_float4(0.f, 0.f, 0.f, 0.f);
            split_bf16(v.x, Ah[arow][acseg + c4 + 0], Al[arow][acseg + c4 + 0]);
            split_bf16(v.y, Ah[arow][acseg + c4 + 1], Al[arow][acseg + c4 + 1]);
            split_bf16(v.z, Ah[arow][acseg + c4 + 2], Al[arow][acseg + c4 + 2]);
            split_bf16(v.w, Ah[arow][acseg + c4 + 3], Al[arow][acseg + c4 + 3]);
        }
        // stage B
        const float* brp = wbase + (size_t)(k0 + brow) * HID_DIM;
#pragma unroll
        for (int c4 = 0; c4 < 16; c4 += 4) {
            float4 v = *(const float4*)(brp + c4);
            split_bf16(v.x, Bh[brow][bcseg + c4 + 0], Bl[brow][bcseg + c4 + 0]);
            split_bf16(v.y, Bh[brow][bcseg + c4 + 1], Bl[brow][bcseg + c4 + 1]);
            split_bf16(v.z, Bh[brow][bcseg + c4 + 2], Bl[brow][bcseg + c4 + 2]);
            split_bf16(v.w, Bh[brow][bcseg + c4 + 3], Bl[brow][bcseg + c4 + 3]);
        }
        __syncthreads();

#pragma unroll
        for (int kk = 0; kk < KCH; kk += 16) {
            wmma::fragment<wmma::matrix_a, 16, 16, 16, __nv_bfloat16, wmma::row_major> fah[2], fal[2];
            wmma::fragment<wmma::matrix_b, 16, 16, 16, __nv_bfloat16, wmma::row_major> fbh[4], fbl[4];
#pragma unroll
            for (int i = 0; i < 2; i++) {
                wmma::load_matrix_sync(fah[i], &Ah[wm * 32 + i * 16][kk], A_LD);
                wmma::load_matrix_sync(fal[i], &Al[wm * 32 + i * 16][kk], A_LD);
            }
#pragma unroll
            for (int j = 0; j < 4; j++) {
                wmma::load_matrix_sync(fbh[j], &Bh[kk][wn * 64 + j * 16], B_LD);
                wmma::load_matrix_sync(fbl[j], &Bl[kk][wn * 64 + j * 16], B_LD);
            }
#pragma unroll
            for (int i = 0; i < 2; i++)
#pragma unroll
                for (int j = 0; j < 4; j++) {
                    wmma::mma_sync(acc[i][j], fah[i], fbh[j], acc[i][j]);
                    wmma::mma_sync(acc[i][j], fal[i], fbh[j], acc[i][j]);
                    wmma::mma_sync(acc[i][j], fah[i], fbl[j], acc[i][j]);
                }
        }
        __syncthreads();
    }

    // epilogue: per-warp patch -> bias + gelu -> g_hidden (fp32)
    const float* b1e = b1 + (size_t)e * HID_DIM + n0;
#pragma unroll
    for (int i = 0; i < 2; i++)
#pragma unroll
        for (int j = 0; j < 4; j++) {
            wmma::store_matrix_sync(cpatch[wid], acc[i][j], 16, wmma::mem_row_major);
            __syncwarp();
            int r0 = wm * 32 + i * 16;
            int c0 = wn * 64 + j * 16;
#pragma unroll
            for (int q = 0; q < 8; q++) {
                int idx = lane * 8 + q;
                int rr = idx >> 4, cc = idx & 15;
                float v = cpatch[wid][idx] + b1e[c0 + cc];
                g_hidden[(size_t)(base + r0 + rr) * HID_DIM + n0 + c0 + cc] = gelu_exact(v);
            }
            __syncwarp();
        }
}

// ---------------- K5: GEMM2  out += w * (h @ w2[e] + b2[e]) ---------------
// grid (MAX_TILES, OUT_DIM/128), block 256.
__global__ __launch_bounds__(256) void gemm2_kernel(
    const float* __restrict__ w2,
    const float* __restrict__ b2,
    float* __restrict__ out) {
    __shared__ __nv_bfloat16 Ah[TILE_M][A_LD];
    __shared__ __nv_bfloat16 Al[TILE_M][A_LD];
    __shared__ __nv_bfloat16 Bh[KCH][B_LD];
    __shared__ __nv_bfloat16 Bl[KCH][B_LD];
    __shared__ float cpatch[8][16 * 16];
    __shared__ int toks[TILE_M];
    __shared__ float wts[TILE_M];

    int tile = blockIdx.x;
    if (tile >= g_num_tiles) return;
    int e = g_tile_expert[tile];
    int base = g_tile_base[tile];
    int n0 = blockIdx.y * TILE_N;
    int tid = threadIdx.x;
    int lane = tid & 31, wid = tid >> 5;
    int wm = wid & 3, wn = wid >> 2;

    if (tid < TILE_M) {
        toks[tid] = g_assign_token[base + tid];
        wts[tid] = g_assign_w[base + tid];
    }
    __syncthreads();

    wmma::fragment<wmma::accumulator, 16, 16, 16, float> acc[2][4];
#pragma unroll
    for (int i = 0; i < 2; i++)
#pragma unroll
        for (int j = 0; j < 4; j++) wmma::fill_fragment(acc[i][j], 0.0f);

    int arow = tid >> 1, acseg = (tid & 1) * 16;
    int brow = tid >> 3, bcseg = (tid & 7) * 16;
    const float* arp = g_hidden + (size_t)(base + arow) * HID_DIM + acseg;
    const float* wbase = w2 + (size_t)e * HID_DIM * OUT_DIM + n0 + bcseg;

    for (int k0 = 0; k0 < HID_DIM; k0 += KCH) {
#pragma unroll
        for (int c4 = 0; c4 < 16; c4 += 4) {
            float4 v = *(const float4*)(arp + k0 + c4);
            split_bf16(v.x, Ah[arow][acseg + c4 + 0], Al[arow][acseg + c4 + 0]);
            split_bf16(v.y, Ah[arow][acseg + c4 + 1], Al[arow][acseg + c4 + 1]);
            split_bf16(v.z, Ah[arow][acseg + c4 + 2], Al[arow][acseg + c4 + 2]);
            split_bf16(v.w, Ah[arow][acseg + c4 + 3], Al[arow][acseg + c4 + 3]);
        }
        const float* brp = wbase + (size_t)(k0 + brow) * OUT_DIM;
#pragma unroll
        for (int c4 = 0; c4 < 16; c4 += 4) {
            float4 v = *(const float4*)(brp + c4);
            split_bf16(v.x, Bh[brow][bcseg + c4 + 0], Bl[brow][bcseg + c4 + 0]);
            split_bf16(v.y, Bh[brow][bcseg + c4 + 1], Bl[brow][bcseg + c4 + 1]);
            split_bf16(v.z, Bh[brow][bcseg + c4 + 2], Bl[brow][bcseg + c4 + 2]);
            split_bf16(v.w, Bh[brow][bcseg + c4 + 3], Bl[brow][bcseg + c4 + 3]);
        }
        __syncthreads();

#pragma unroll
        for (int kk = 0; kk < KCH; kk += 16) {
            wmma::fragment<wmma::matrix_a, 16, 16, 16, __nv_bfloat16, wmma::row_major> fah[2], fal[2];
            wmma::fragment<wmma::matrix_b, 16, 16, 16, __nv_bfloat16, wmma::row_major> fbh[4], fbl[4];
#pragma unroll
            for (int i = 0; i < 2; i++) {
                wmma::load_matrix_sync(fah[i], &Ah[wm * 32 + i * 16][kk], A_LD);
                wmma::load_matrix_sync(fal[i], &Al[wm * 32 + i * 16][kk], A_LD);
            }
#pragma unroll
            for (int j = 0; j < 4; j++) {
                wmma::load_matrix_sync(fbh[j], &Bh[kk][wn * 64 + j * 16], B_LD);
                wmma::load_matrix_sync(fbl[j], &Bl[kk][wn * 64 + j * 16], B_LD);
            }
#pragma unroll
            for (int i = 0; i < 2; i++)
#pragma unroll
                for (int j = 0; j < 4; j++) {
                    wmma::mma_sync(acc[i][j], fah[i], fbh[j], acc[i][j]);
                    wmma::mma_sync(acc[i][j], fal[i], fbh[j], acc[i][j]);
                    wmma::mma_sync(acc[i][j], fah[i], fbl[j], acc[i][j]);
                }
        }
        __syncthreads();
    }

    const float* b2e = b2 + (size_t)e * OUT_DIM + n0;
#pragma unroll
    for (int i = 0; i < 2; i++)
#pragma unroll
        for (int j = 0; j < 4; j++) {
            wmma::store_matrix_sync(cpatch[wid], acc[i][j], 16, wmma::mem_row_major);
            __syncwarp();
            int r0 = wm * 32 + i * 16;
            int c0 = wn * 64 + j * 16;
#pragma unroll
            for (int q = 0; q < 8; q++) {
                int idx = lane * 8 + q;
                int rr = idx >> 4, cc = idx & 15;
                int t = toks[r0 + rr];
                if (t >= 0) {
                    float v = (cpatch[wid][idx] + b2e[c0 + cc]) * wts[r0 + rr];
                    atomicAdd(&out[(size_t)t * OUT_DIM + n0 + c0 + cc], v);
                }
            }
            __syncwarp();
        }
}

// ---------------- launch ---------------------------------------------------
extern "C" void kernel_launch(void* const* d_in, const int* in_sizes, int n_in,
                              void* d_out, int out_size) {
    const float* x      = (const float*)d_in[0];
    const float* gate_w = (const float*)d_in[1];
    const float* gate_b = (const float*)d_in[2];
    const float* w1     = (const float*)d_in[3];
    const float* b1     = (const float*)d_in[4];
    const float* w2     = (const float*)d_in[5];
    const float* b2     = (const float*)d_in[6];
    float* out = (float*)d_out;

    {
        size_t total = (size_t)NTOK * OUT_DIM;
        zero_kernel<<<(int)((total + 255) / 256), 256>>>(out);
    }
    gating_kernel<<<NTOK / 8, 256>>>(x, gate_w, gate_b);
    setup_kernel<<<1, 32>>>(out, out_size);
    scatter_kernel<<<NTOK / 256, 256>>>();
    {
        dim3 grid(MAX_TILES, HID_DIM / TILE_N);   // 264 x 8
        gemm1_kernel<<<grid, 256>>>(x, w1, b1);
    }
    {
        dim3 grid(MAX_TILES, OUT_DIM / TILE_N);   // 264 x 4
        gemm2_kernel<<<grid, 256>>>(w2, b2, out);
    }
}

// round 8
// speedup vs baseline: 2.0361x; 1.8780x over previous
#include <cuda_runtime.h>
#include <cuda_bf16.h>
#include <mma.h>
#include <math.h>
#include <stdint.h>

using namespace nvcuda;

#define N_EXPERTS 8
#define TOPK      2
#define IN_DIM    512
#define HID_DIM   1024
#define OUT_DIM   512
#define NTOK      16384

#define TILE_M 128
#define TILE_N 128
#define MAX_TILES ((NTOK * TOPK) / TILE_M + N_EXPERTS)   // 264
#define PADDED    (MAX_TILES * TILE_M)                    // 33792

#define KCH 16
#define NC1 (IN_DIM / KCH)    // 32
#define NC2 (HID_DIM / KCH)   // 64

// static smem stage layout (bytes); all offsets 16B aligned
#define A_LD 24               // bf16 elems per A row (16 data + pad)
#define A_ROWB (A_LD * 2)     // 48
#define B_LD 136              // bf16 elems per B row (128 data + pad)
#define B_ROWB (B_LD * 2)     // 272
#define AH_OFF 0
#define AL_OFF (TILE_M * A_ROWB)              // 6144
#define BH_OFF (2 * TILE_M * A_ROWB)          // 12288
#define BL_OFF (BH_OFF + KCH * B_ROWB)        // 16640
#define STAGE_BYTES (BL_OFF + KCH * B_ROWB)   // 20992
#define SMEM_TOTAL (2 * STAGE_BYTES)          // 41984  (< 48KB static)

// ---------------- device scratch (referenced from DEVICE code only!) -------
__device__ int   g_topk_idx[NTOK * TOPK];
__device__ float g_topk_w[NTOK * TOPK];
__device__ int   g_counts[N_EXPERTS];
__device__ int   g_cursor[N_EXPERTS];
__device__ int   g_tile_expert[MAX_TILES];
__device__ int   g_tile_base[MAX_TILES];
__device__ int   g_num_tiles;
__device__ int   g_assign_token[PADDED];
__device__ float g_assign_w[PADDED];

__device__ __align__(16) __nv_bfloat16 g_xh[(size_t)NTOK * IN_DIM];
__device__ __align__(16) __nv_bfloat16 g_xl[(size_t)NTOK * IN_DIM];
__device__ __align__(16) __nv_bfloat16 g_w1h[(size_t)N_EXPERTS * IN_DIM * HID_DIM];
__device__ __align__(16) __nv_bfloat16 g_w1l[(size_t)N_EXPERTS * IN_DIM * HID_DIM];
__device__ __align__(16) __nv_bfloat16 g_w2h[(size_t)N_EXPERTS * HID_DIM * OUT_DIM];
__device__ __align__(16) __nv_bfloat16 g_w2l[(size_t)N_EXPERTS * HID_DIM * OUT_DIM];
__device__ __align__(16) __nv_bfloat16 g_hidh[(size_t)PADDED * HID_DIM];
__device__ __align__(16) __nv_bfloat16 g_hidl[(size_t)PADDED * HID_DIM];

// ---------------- helpers ----------------
__device__ __forceinline__ float gelu_exact(float v) {
    return 0.5f * v * (1.0f + erff(v * 0.70710678118654752440f));
}
__device__ __forceinline__ void split_bf16(float v, __nv_bfloat16& h, __nv_bfloat16& l) {
    h = __float2bfloat16(v);
    l = __float2bfloat16(v - __bfloat162float(h));
}

// ---------------- K0: zero output, counts, assignment padding ------------
__global__ void zero_kernel(float* __restrict__ out) {
    size_t idx = (size_t)blockIdx.x * blockDim.x + threadIdx.x;
    size_t total = (size_t)NTOK * OUT_DIM;
    if (idx < total) out[idx] = 0.0f;
    if (idx < PADDED) g_assign_token[idx] = -1;
    if (idx < N_EXPERTS) g_counts[idx] = 0;
}

// ---------------- K0b: fp32 -> bf16 hi/lo splits (globals referenced in-kernel)
__device__ __forceinline__ void split4(const float* __restrict__ src, size_t i,
                                       __nv_bfloat16* __restrict__ dh,
                                       __nv_bfloat16* __restrict__ dl) {
    float4 v = *(const float4*)(src + i * 4);
    __nv_bfloat16 h[4], l[4];
    split_bf16(v.x, h[0], l[0]);
    split_bf16(v.y, h[1], l[1]);
    split_bf16(v.z, h[2], l[2]);
    split_bf16(v.w, h[3], l[3]);
    *(uint2*)(dh + i * 4) = *(uint2*)h;
    *(uint2*)(dl + i * 4) = *(uint2*)l;
}
__global__ void split_x_kernel(const float* __restrict__ src) {
    size_t i = (size_t)blockIdx.x * blockDim.x + threadIdx.x;
    if (i < (size_t)NTOK * IN_DIM / 4) split4(src, i, g_xh, g_xl);
}
__global__ void split_w1_kernel(const float* __restrict__ src) {
    size_t i = (size_t)blockIdx.x * blockDim.x + threadIdx.x;
    if (i < (size_t)N_EXPERTS * IN_DIM * HID_DIM / 4) split4(src, i, g_w1h, g_w1l);
}
__global__ void split_w2_kernel(const float* __restrict__ src) {
    size_t i = (size_t)blockIdx.x * blockDim.x + threadIdx.x;
    if (i < (size_t)N_EXPERTS * HID_DIM * OUT_DIM / 4) split4(src, i, g_w2h, g_w2l);
}

// ---------------- K1: gating — one warp per token -------------------------
__global__ void gating_kernel(const float* __restrict__ x,
                              const float* __restrict__ gw,
                              const float* __restrict__ gb) {
    int token = blockIdx.x * (blockDim.x >> 5) + (threadIdx.x >> 5);
    if (token >= NTOK) return;
    int lane = threadIdx.x & 31;
    float s[N_EXPERTS];
#pragma unroll
    for (int e = 0; e < N_EXPERTS; e++) s[e] = 0.0f;
    const float* xr = x + (size_t)token * IN_DIM;
    for (int i = lane; i < IN_DIM; i += 32) {
        float xv = xr[i];
        const float* g = gw + (size_t)i * N_EXPERTS;
#pragma unroll
        for (int e = 0; e < N_EXPERTS; e++) s[e] += xv * g[e];
    }
#pragma unroll
    for (int off = 16; off > 0; off >>= 1)
#pragma unroll
        for (int e = 0; e < N_EXPERTS; e++)
            s[e] += __shfl_xor_sync(0xFFFFFFFFu, s[e], off);
    if (lane == 0) {
#pragma unroll
        for (int e = 0; e < N_EXPERTS; e++) s[e] += gb[e];
        float v0 = -INFINITY; int i0 = -1;
#pragma unroll
        for (int e = 0; e < N_EXPERTS; e++)
            if (s[e] > v0) { v0 = s[e]; i0 = e; }
        float v1 = -INFINITY; int i1 = -1;
#pragma unroll
        for (int e = 0; e < N_EXPERTS; e++)
            if (e != i0 && s[e] > v1) { v1 = s[e]; i1 = e; }
        float e1 = expf(v1 - v0);
        float inv = 1.0f / (1.0f + e1);
        g_topk_idx[token * 2 + 0] = i0;
        g_topk_idx[token * 2 + 1] = i1;
        g_topk_w[token * 2 + 0] = inv;
        g_topk_w[token * 2 + 1] = e1 * inv;
        atomicAdd(&g_counts[i0], 1);
        atomicAdd(&g_counts[i1], 1);
    }
}

// ---------------- K2: setup — tile table, cursors, aux loss ---------------
__global__ void setup_kernel(float* __restrict__ out, int out_size) {
    if (threadIdx.x != 0 || blockIdx.x != 0) return;
    int nt = 0, off = 0;
    for (int e = 0; e < N_EXPERTS; e++) {
        int c = g_counts[e];
        int tiles = (c + TILE_M - 1) / TILE_M;
        g_cursor[e] = off;
        for (int i = 0; i < tiles; i++) {
            g_tile_expert[nt] = e;
            g_tile_base[nt] = off + i * TILE_M;
            nt++;
        }
        off += tiles * TILE_M;
    }
    g_num_tiles = nt;
    float aux = 0.0f;
    for (int e = 0; e < N_EXPERTS; e++) {
        float f = (float)g_counts[e] / (float)(NTOK * TOPK) - 1.0f / N_EXPERTS;
        aux += f * f;
    }
    aux *= (1.0f / N_EXPERTS);
    if (out_size > NTOK * OUT_DIM) out[(size_t)NTOK * OUT_DIM] = aux;
}

// ---------------- K3: scatter tokens to expert segments -------------------
__global__ void scatter_kernel() {
    int t = blockIdx.x * blockDim.x + threadIdx.x;
    if (t >= NTOK) return;
#pragma unroll
    for (int k = 0; k < TOPK; k++) {
        int e = g_topk_idx[t * 2 + k];
        int pos = atomicAdd(&g_cursor[e], 1);
        g_assign_token[pos] = t;
        g_assign_w[pos] = g_topk_w[t * 2 + k];
    }
}

// ---------------- staged chunk regs ----------------
struct Pref { uint4 ah, al, bh, bl; };

__device__ __forceinline__ void sts_stage(uint8_t* st, int ar, int ac8, int br, int bc8,
                                          const Pref& p) {
    *(uint4*)(st + AH_OFF + ar * A_ROWB + ac8 * 2) = p.ah;
    *(uint4*)(st + AL_OFF + ar * A_ROWB + ac8 * 2) = p.al;
    *(uint4*)(st + BH_OFF + br * B_ROWB + bc8 * 2) = p.bh;
    *(uint4*)(st + BL_OFF + br * B_ROWB + bc8 * 2) = p.bl;
}

// ---------------- wmma compute for one staged chunk (single K=16 step) ----
__device__ __forceinline__ void compute_chunk(
    uint8_t* sb, int wm, int wn,
    wmma::fragment<wmma::accumulator, 16, 16, 16, float> acc[2][4]) {
    __nv_bfloat16* Ah = (__nv_bfloat16*)(sb + AH_OFF);
    __nv_bfloat16* Al = (__nv_bfloat16*)(sb + AL_OFF);
    __nv_bfloat16* Bh = (__nv_bfloat16*)(sb + BH_OFF);
    __nv_bfloat16* Bl = (__nv_bfloat16*)(sb + BL_OFF);
    wmma::fragment<wmma::matrix_a, 16, 16, 16, __nv_bfloat16, wmma::row_major> fah[2], fal[2];
    wmma::fragment<wmma::matrix_b, 16, 16, 16, __nv_bfloat16, wmma::row_major> fbh[4], fbl[4];
#pragma unroll
    for (int i = 0; i < 2; i++) {
        wmma::load_matrix_sync(fah[i], Ah + (wm * 32 + i * 16) * A_LD, A_LD);
        wmma::load_matrix_sync(fal[i], Al + (wm * 32 + i * 16) * A_LD, A_LD);
    }
#pragma unroll
    for (int j = 0; j < 4; j++) {
        wmma::load_matrix_sync(fbh[j], Bh + wn * 64 + j * 16, B_LD);
        wmma::load_matrix_sync(fbl[j], Bl + wn * 64 + j * 16, B_LD);
    }
#pragma unroll
    for (int i = 0; i < 2; i++)
#pragma unroll
        for (int j = 0; j < 4; j++) {
            wmma::mma_sync(acc[i][j], fah[i], fbh[j], acc[i][j]);
            wmma::mma_sync(acc[i][j], fal[i], fbh[j], acc[i][j]);
            wmma::mma_sync(acc[i][j], fah[i], fbl[j], acc[i][j]);
        }
}

// ---------------- K4: GEMM1  h = gelu(x_sel @ w1[e] + b1[e]) --------------
__global__ __launch_bounds__(256) void gemm1_kernel(const float* __restrict__ b1) {
    __shared__ __align__(16) uint8_t sm[SMEM_TOTAL];
    __shared__ int toks[TILE_M];

    int tile = blockIdx.x;
    if (tile >= g_num_tiles) return;
    int e = g_tile_expert[tile];
    int base = g_tile_base[tile];
    int n0 = blockIdx.y * TILE_N;
    int tid = threadIdx.x;
    int lane = tid & 31, wid = tid >> 5;
    int wm = wid & 3, wn = wid >> 2;

    if (tid < TILE_M) toks[tid] = g_assign_token[base + tid];
    __syncthreads();

    int ar = tid >> 1, ac8 = (tid & 1) * 8;
    int br = tid >> 4, bc8 = (tid & 15) * 8;
    int atok = toks[ar];
    const __nv_bfloat16* axh = (atok >= 0) ? (g_xh + (size_t)atok * IN_DIM + ac8) : nullptr;
    const __nv_bfloat16* axl = (atok >= 0) ? (g_xl + (size_t)atok * IN_DIM + ac8) : nullptr;
    const __nv_bfloat16* bwh = g_w1h + ((size_t)e * IN_DIM + br) * HID_DIM + n0 + bc8;
    const __nv_bfloat16* bwl = g_w1l + ((size_t)e * IN_DIM + br) * HID_DIM + n0 + bc8;

    wmma::fragment<wmma::accumulator, 16, 16, 16, float> acc[2][4];
#pragma unroll
    for (int i = 0; i < 2; i++)
#pragma unroll
        for (int j = 0; j < 4; j++) wmma::fill_fragment(acc[i][j], 0.0f);

    Pref p;
    const uint4 z4 = make_uint4(0, 0, 0, 0);
    p.ah = axh ? *(const uint4*)axh : z4;
    p.al = axl ? *(const uint4*)axl : z4;
    p.bh = *(const uint4*)bwh;
    p.bl = *(const uint4*)bwl;

    for (int c = 0; c < NC1; c++) {
        sts_stage(sm + (c & 1) * STAGE_BYTES, ar, ac8, br, bc8, p);
        if (c + 1 < NC1) {
            int k0 = (c + 1) * KCH;
            p.ah = axh ? *(const uint4*)(axh + k0) : z4;
            p.al = axl ? *(const uint4*)(axl + k0) : z4;
            p.bh = *(const uint4*)(bwh + (size_t)k0 * HID_DIM);
            p.bl = *(const uint4*)(bwl + (size_t)k0 * HID_DIM);
        }
        __syncthreads();
        compute_chunk(sm + (c & 1) * STAGE_BYTES, wm, wn, acc);
    }
    __syncthreads();

    float* cpatch = (float*)sm + wid * 256;
    const float* b1e = b1 + (size_t)e * HID_DIM + n0;
#pragma unroll
    for (int i = 0; i < 2; i++)
#pragma unroll
        for (int j = 0; j < 4; j++) {
            wmma::store_matrix_sync(cpatch, acc[i][j], 16, wmma::mem_row_major);
            __syncwarp();
            int r0 = wm * 32 + i * 16;
            int c0 = wn * 64 + j * 16;
            int rr = (lane * 8) >> 4;
            int cc = (lane * 8) & 15;
            __nv_bfloat16 hbuf[8], lbuf[8];
#pragma unroll
            for (int q = 0; q < 8; q++) {
                float v = gelu_exact(cpatch[lane * 8 + q] + b1e[c0 + cc + q]);
                split_bf16(v, hbuf[q], lbuf[q]);
            }
            size_t di = (size_t)(base + r0 + rr) * HID_DIM + n0 + c0 + cc;
            *(uint4*)(g_hidh + di) = *(uint4*)hbuf;
            *(uint4*)(g_hidl + di) = *(uint4*)lbuf;
            __syncwarp();
        }
}

// ---------------- K5: GEMM2  out += w * (h @ w2[e] + b2[e]) ---------------
__global__ __launch_bounds__(256) void gemm2_kernel(const float* __restrict__ b2,
                                                    float* __restrict__ out) {
    __shared__ __align__(16) uint8_t sm[SMEM_TOTAL];
    __shared__ int toks[TILE_M];
    __shared__ float wts[TILE_M];

    int tile = blockIdx.x;
    if (tile >= g_num_tiles) return;
    int e = g_tile_expert[tile];
    int base = g_tile_base[tile];
    int n0 = blockIdx.y * TILE_N;
    int tid = threadIdx.x;
    int lane = tid & 31, wid = tid >> 5;
    int wm = wid & 3, wn = wid >> 2;

    if (tid < TILE_M) {
        toks[tid] = g_assign_token[base + tid];
        wts[tid] = g_assign_w[base + tid];
    }
    __syncthreads();

    int ar = tid >> 1, ac8 = (tid & 1) * 8;
    int br = tid >> 4, bc8 = (tid & 15) * 8;
    const __nv_bfloat16* axh = g_hidh + (size_t)(base + ar) * HID_DIM + ac8;
    const __nv_bfloat16* axl = g_hidl + (size_t)(base + ar) * HID_DIM + ac8;
    const __nv_bfloat16* bwh = g_w2h + ((size_t)e * HID_DIM + br) * OUT_DIM + n0 + bc8;
    const __nv_bfloat16* bwl = g_w2l + ((size_t)e * HID_DIM + br) * OUT_DIM + n0 + bc8;

    wmma::fragment<wmma::accumulator, 16, 16, 16, float> acc[2][4];
#pragma unroll
    for (int i = 0; i < 2; i++)
#pragma unroll
        for (int j = 0; j < 4; j++) wmma::fill_fragment(acc[i][j], 0.0f);

    Pref p;
    p.ah = *(const uint4*)axh;
    p.al = *(const uint4*)axl;
    p.bh = *(const uint4*)bwh;
    p.bl = *(const uint4*)bwl;

    for (int c = 0; c < NC2; c++) {
        sts_stage(sm + (c & 1) * STAGE_BYTES, ar, ac8, br, bc8, p);
        if (c + 1 < NC2) {
            int k0 = (c + 1) * KCH;
            p.ah = *(const uint4*)(axh + k0);
            p.al = *(const uint4*)(axl + k0);
            p.bh = *(const uint4*)(bwh + (size_t)k0 * OUT_DIM);
            p.bl = *(const uint4*)(bwl + (size_t)k0 * OUT_DIM);
        }
        __syncthreads();
        compute_chunk(sm + (c & 1) * STAGE_BYTES, wm, wn, acc);
    }
    __syncthreads();

    float* cpatch = (float*)sm + wid * 256;
    const float* b2e = b2 + (size_t)e * OUT_DIM + n0;
#pragma unroll
    for (int i = 0; i < 2; i++)
#pragma unroll
        for (int j = 0; j < 4; j++) {
            wmma::store_matrix_sync(cpatch, acc[i][j], 16, wmma::mem_row_major);
            __syncwarp();
            int r0 = wm * 32 + i * 16;
            int c0 = wn * 64 + j * 16;
            int rr = (lane * 8) >> 4;
            int cc = (lane * 8) & 15;
            int t = toks[r0 + rr];
            if (t >= 0) {
                float wt = wts[r0 + rr];
                float* orow = out + (size_t)t * OUT_DIM + n0 + c0 + cc;
#pragma unroll
                for (int q = 0; q < 8; q++) {
                    float v = (cpatch[lane * 8 + q] + b2e[c0 + cc + q]) * wt;
                    atomicAdd(&orow[q], v);
                }
            }
            __syncwarp();
        }
}

// ---------------- launch ---------------------------------------------------
extern "C" void kernel_launch(void* const* d_in, const int* in_sizes, int n_in,
                              void* d_out, int out_size) {
    const float* x      = (const float*)d_in[0];
    const float* gate_w = (const float*)d_in[1];
    const float* gate_b = (const float*)d_in[2];
    const float* w1     = (const float*)d_in[3];
    const float* b1     = (const float*)d_in[4];
    const float* w2     = (const float*)d_in[5];
    const float* b2     = (const float*)d_in[6];
    float* out = (float*)d_out;

    {
        size_t total = (size_t)NTOK * OUT_DIM;
        zero_kernel<<<(int)((total + 255) / 256), 256>>>(out);
    }
    {
        size_t nx = (size_t)NTOK * IN_DIM / 4;
        split_x_kernel<<<(int)((nx + 255) / 256), 256>>>(x);
        size_t n1 = (size_t)N_EXPERTS * IN_DIM * HID_DIM / 4;
        split_w1_kernel<<<(int)((n1 + 255) / 256), 256>>>(w1);
        size_t n2 = (size_t)N_EXPERTS * HID_DIM * OUT_DIM / 4;
        split_w2_kernel<<<(int)((n2 + 255) / 256), 256>>>(w2);
    }
    gating_kernel<<<NTOK / 8, 256>>>(x, gate_w, gate_b);
    setup_kernel<<<1, 32>>>(out, out_size);
    scatter_kernel<<<NTOK / 256, 256>>>();
    {
        dim3 grid(MAX_TILES, HID_DIM / TILE_N);   // 264 x 8
        gemm1_kernel<<<grid, 256>>>(b1);
    }
    {
        dim3 grid(MAX_TILES, OUT_DIM / TILE_N);   // 264 x 4
        gemm2_kernel<<<grid, 256>>>(b2, out);
    }
}